// round 10
// baseline (speedup 1.0000x reference)
#include <cuda_runtime.h>
#include <math.h>

#define Bq 4
#define Cc 32
#define Hh 128
#define Ww 128
#define HW (Hh*Ww)
#define BHW (Bq*HW)
#define MSIZE 512
#define HD 8

typedef unsigned long long ull;

__device__ __forceinline__ ull pk2(float lo, float hi) {
    ull r; asm("mov.b64 %0,{%1,%2};" : "=l"(r) : "f"(lo), "f"(hi)); return r;
}
__device__ __forceinline__ void upk2(float& lo, float& hi, ull v) {
    asm("mov.b64 {%0,%1},%2;" : "=f"(lo), "=f"(hi) : "l"(v));
}
__device__ __forceinline__ void fma2(ull& d, ull a, ull b, ull c) {
    asm("fma.rn.f32x2 %0,%1,%2,%3;" : "=l"(d) : "l"(a), "l"(b), "l"(c));
}
__device__ __forceinline__ void mul2(ull& d, ull a, ull b) {
    asm("mul.rn.f32x2 %0,%1,%2;" : "=l"(d) : "l"(a), "l"(b));
}
__device__ __forceinline__ void add2(ull& d, ull a, ull b) {
    asm("add.rn.f32x2 %0,%1,%2;" : "=l"(d) : "l"(a), "l"(b));
}
__device__ __forceinline__ float ex2f(float x) {
    float r; asm("ex2.approx.f32 %0,%1;" : "=f"(r) : "f"(x)); return r;
}

// scratch (no allocs allowed)
__device__ float g_xt[BHW*Cc];     // x transposed to NHWC: [b][y*128+x][c]
__device__ float g_x3t[BHW*Cc];    // dcn output, NHWC: [p][o]
__device__ float g_om[27*BHW];     // offset-conv output, [j][p]
__device__ float g_yavg[Bq*Cc];
__device__ float g_ysp[Bq*Cc];
__device__ float g_ych[Bq*Cc];

// ---------------- kernel 0: NCHW -> NHWC transpose ----------------
__global__ __launch_bounds__(256) void k_tr(const float* __restrict__ x) {
    __shared__ float t[128][33];           // [px][c], padded
    int tid = threadIdx.x;
    int b = blockIdx.x >> 7, y = blockIdx.x & 127;
    const float* xb = x + ((long)b << 19) + y*128;
    for (int i = tid; i < 4096; i += 256) {
        int c = i >> 7, px = i & 127;
        t[px][c] = xb[(c << 14) + px];
    }
    __syncthreads();
    float4* dst = (float4*)(g_xt + ((long)((b << 14) + y*128))*32);
    for (int i = tid; i < 1024; i += 256) {
        int px = i >> 3, c4 = (i & 7)*4;
        dst[i] = make_float4(t[px][c4], t[px][c4+1], t[px][c4+2], t[px][c4+3]);
    }
}

// ---------------- kernel 1: per-(b,c) spatial mean ----------------
__global__ void k_avg(const float* __restrict__ x) {
    int bc = blockIdx.x;
    const float* p = x + bc * HW;
    float s = 0.f;
    for (int i = threadIdx.x; i < HW; i += 256) s += p[i];
    __shared__ float red[256];
    red[threadIdx.x] = s; __syncthreads();
    for (int st = 128; st > 0; st >>= 1) {
        if (threadIdx.x < st) red[threadIdx.x] += red[threadIdx.x + st];
        __syncthreads();
    }
    if (threadIdx.x == 0) g_yavg[bc] = red[0] * (1.0f / (float)HW);
}

// ---------------- kernel 2: tiny squeeze MLPs ----------------
__global__ void k_mlp(const float* __restrict__ fs_w1, const float* __restrict__ fs_w2,
                      const float* __restrict__ fc_w1, const float* __restrict__ fc_w2) {
    __shared__ float ys[Bq*Cc];
    int t = threadIdx.x;           // 128 threads, t = b*32+c
    ys[t] = g_yavg[t];
    __syncthreads();
    int b = t >> 5, c = t & 31;
    const float* yb = ys + b * 32;
    float hs0 = 0.f, hs1 = 0.f;
    #pragma unroll
    for (int j = 0; j < 32; j++) { hs0 += yb[j] * fs_w1[j]; hs1 += yb[j] * fs_w1[32 + j]; }
    hs0 = fmaxf(hs0, 0.f); hs1 = fmaxf(hs1, 0.f);
    float sp = hs0 * fs_w2[c*2 + 0] + hs1 * fs_w2[c*2 + 1];
    g_ysp[t] = 1.f / (1.f + __expf(-sp));
    float ch = 0.f;
    #pragma unroll
    for (int r = 0; r < 4; r++) {
        float a = 0.f;
        #pragma unroll
        for (int j = 0; j < 32; j++) a += yb[j] * fc_w1[r*32 + j];
        ch += fmaxf(a, 0.f) * fc_w2[c*4 + r];
    }
    g_ych[t] = 1.f / (1.f + __expf(-ch));
}

// ---------------- kernel 3a: offset conv (3x3, 32->27), NHWC loads ----------------
__global__ __launch_bounds__(256) void k_off(
    const float* __restrict__ off_w, const float* __restrict__ off_b)
{
    __shared__ __align__(16) float wbuf[9*32*28];   // woff[k][c][j28]  32.2KB
    __shared__ float bbuf[28];
    int tid = threadIdx.x;
    for (int i = tid; i < 7776; i += 256) {
        int j = i / 288, r = i - j*288, c = r / 9, k = r - c*9;
        wbuf[(k*32 + c)*28 + j] = off_w[i];
    }
    for (int i = tid; i < 288; i += 256) wbuf[i*28 + 27] = 0.f;
    if (tid < 27) bbuf[tid] = off_b[tid];
    if (tid == 27) bbuf[27] = 0.f;
    __syncthreads();

    int p = blockIdx.x * 256 + tid;
    int b = p >> 14, rem = p & 16383;
    int y = rem >> 7, x0i = rem & 127;
    const float* xtb = g_xt + ((long)(b << 14))*32;

    ull om2[14];
    #pragma unroll
    for (int j = 0; j < 14; j++) om2[j] = pk2(bbuf[2*j], bbuf[2*j+1]);

    for (int ky = 0; ky < 3; ky++) {
        int yy = y + ky - 1;
        if (yy < 0 || yy > 127) continue;
        for (int kx = 0; kx < 3; kx++) {
            int xx = x0i + kx - 1;
            if (xx < 0 || xx > 127) continue;
            int kidx = ky*3 + kx;
            const float4* xp = (const float4*)(xtb + ((long)(yy*128 + xx))*32);
            const float* wb0 = wbuf + kidx*32*28;
            #pragma unroll
            for (int c4 = 0; c4 < 8; c4++) {
                float4 v = xp[c4];
                float vs[4] = {v.x, v.y, v.z, v.w};
                #pragma unroll
                for (int q = 0; q < 4; q++) {
                    ull v2 = pk2(vs[q], vs[q]);
                    const ulonglong2* wp = (const ulonglong2*)(wb0 + (c4*4 + q)*28);
                    #pragma unroll
                    for (int i = 0; i < 7; i++) {
                        ulonglong2 u = wp[i];
                        fma2(om2[2*i],   v2, u.x, om2[2*i]);
                        fma2(om2[2*i+1], v2, u.y, om2[2*i+1]);
                    }
                }
            }
        }
    }
    #pragma unroll
    for (int j = 0; j < 13; j++) {
        float a, bb; upk2(a, bb, om2[j]);
        g_om[(2*j)*BHW + p]   = a;
        g_om[(2*j+1)*BHW + p] = bb;
    }
    { float a, bb; upk2(a, bb, om2[13]); g_om[26*BHW + p] = a; }
}

// ---------------- kernel 3b: deformable gather + 3x3 conv, NHWC ----------------
__global__ __launch_bounds__(256) void k_dcn2(
    const float* __restrict__ dcn_w, const float* __restrict__ dcn_b)
{
    __shared__ __align__(16) float wbuf[9216];   // wdcn[k][c][o32], 36.9KB
    __shared__ float bbuf[32];
    int tid = threadIdx.x;
    for (int i = tid; i < 9216; i += 256) {
        int o = i / 288, r = i - o*288, c = r / 9, k = r - c*9;
        wbuf[(k*32 + c)*32 + o] = dcn_w[i];
    }
    if (tid < 32) bbuf[tid] = dcn_b[tid];
    __syncthreads();

    int p = blockIdx.x * 256 + tid;
    int b = p >> 14, rem = p & 16383;
    int y = rem >> 7, x0i = rem & 127;
    const float* xtb = g_xt + ((long)(b << 14))*32;

    ull acc2[16];   // acc2[j] = outputs (2j, 2j+1)
    #pragma unroll
    for (int i = 0; i < 16; i++) acc2[i] = pk2(bbuf[2*i], bbuf[2*i+1]);

    for (int k = 0; k < 9; k++) {
        float ofy = g_om[(2*k)*BHW + p];
        float ofx = g_om[(2*k+1)*BHW + p];
        float msk = 1.f / (1.f + __expf(-g_om[(18+k)*BHW + p]));
        float py = (float)(y   + k/3 - 1) + ofy;
        float px = (float)(x0i + k%3 - 1) + ofx;
        py = fminf(fmaxf(py, -4.0f), 131.0f);
        px = fminf(fmaxf(px, -4.0f), 131.0f);
        float fy = floorf(py), fx = floorf(px);
        float wy = py - fy, wx = px - fx;
        int iy0 = (int)fy, ix0 = (int)fx, iy1 = iy0+1, ix1 = ix0+1;
        float vy0 = (iy0 >= 0 && iy0 <= 127) ? 1.f : 0.f;
        float vy1 = (iy1 >= 0 && iy1 <= 127) ? 1.f : 0.f;
        float vx0 = (ix0 >= 0 && ix0 <= 127) ? 1.f : 0.f;
        float vx1 = (ix1 >= 0 && ix1 <= 127) ? 1.f : 0.f;
        float w00 = (1.f-wy)*(1.f-wx)*vy0*vx0*msk;
        float w01 = (1.f-wy)*wx      *vy0*vx1*msk;
        float w10 = wy      *(1.f-wx)*vy1*vx0*msk;
        float w11 = wy      *wx      *vy1*vx1*msk;
        int cy0 = min(max(iy0,0),127), cy1 = min(max(iy1,0),127);
        int cx0 = min(max(ix0,0),127), cx1 = min(max(ix1,0),127);
        const float4* p00 = (const float4*)(xtb + ((long)(cy0*128+cx0))*32);
        const float4* p01 = (const float4*)(xtb + ((long)(cy0*128+cx1))*32);
        const float4* p10 = (const float4*)(xtb + ((long)(cy1*128+cx0))*32);
        const float4* p11 = (const float4*)(xtb + ((long)(cy1*128+cx1))*32);
        ull w002 = pk2(w00,w00), w012 = pk2(w01,w01);
        ull w102 = pk2(w10,w10), w112 = pk2(w11,w11);

        ull samp2[16];   // samp2[j] = channels (2j, 2j+1)
        #pragma unroll
        for (int i = 0; i < 8; i++) {
            float4 v = p00[i];
            mul2(samp2[2*i],   w002, pk2(v.x, v.y));
            mul2(samp2[2*i+1], w002, pk2(v.z, v.w));
        }
        #pragma unroll
        for (int i = 0; i < 8; i++) {
            float4 v = p01[i];
            fma2(samp2[2*i],   w012, pk2(v.x, v.y), samp2[2*i]);
            fma2(samp2[2*i+1], w012, pk2(v.z, v.w), samp2[2*i+1]);
        }
        #pragma unroll
        for (int i = 0; i < 8; i++) {
            float4 v = p10[i];
            fma2(samp2[2*i],   w102, pk2(v.x, v.y), samp2[2*i]);
            fma2(samp2[2*i+1], w102, pk2(v.z, v.w), samp2[2*i+1]);
        }
        #pragma unroll
        for (int i = 0; i < 8; i++) {
            float4 v = p11[i];
            fma2(samp2[2*i],   w112, pk2(v.x, v.y), samp2[2*i]);
            fma2(samp2[2*i+1], w112, pk2(v.z, v.w), samp2[2*i+1]);
        }
        // conv: out[o] += samp[c] * w[k][c][o]; weight row per channel = 32 floats
        const float* wb0 = wbuf + k*1024;
        #pragma unroll 2
        for (int cp = 0; cp < 16; cp++) {
            float va, vb; upk2(va, vb, samp2[cp]);
            ull va2 = pk2(va, va), vb2 = pk2(vb, vb);
            const ulonglong2* wpa = (const ulonglong2*)(wb0 + (2*cp)*32);
            const ulonglong2* wpb = (const ulonglong2*)(wb0 + (2*cp+1)*32);
            #pragma unroll
            for (int i = 0; i < 8; i++) {
                ulonglong2 ua = wpa[i];
                fma2(acc2[2*i],   va2, ua.x, acc2[2*i]);
                fma2(acc2[2*i+1], va2, ua.y, acc2[2*i+1]);
            }
            #pragma unroll
            for (int i = 0; i < 8; i++) {
                ulonglong2 ub = wpb[i];
                fma2(acc2[2*i],   vb2, ub.x, acc2[2*i]);
                fma2(acc2[2*i+1], vb2, ub.y, acc2[2*i+1]);
            }
        }
    }
    // write NHWC: g_x3t[p][o], contiguous float4 stores
    float4* x3q = (float4*)(g_x3t + (long)p*32);
    #pragma unroll
    for (int i = 0; i < 8; i++) {
        float a0, a1, a2v, a3; upk2(a0, a1, acc2[2*i]); upk2(a2v, a3, acc2[2*i+1]);
        x3q[i] = make_float4(a0, a1, a2v, a3);
    }
}

// ---------------- kernel 4: switch-conv + gates -> xo (writes out) ----------------
__global__ __launch_bounds__(256) void k_conv(
    const float* __restrict__ sw_w1, const float* __restrict__ sw_b1,
    const float* __restrict__ sw_w2, const float* __restrict__ sw_b2,
    float* __restrict__ out)
{
    __shared__ __align__(16) float w1t[64*32];       // transposed: w1t[c][o]
    __shared__ __align__(16) ull   w2p[32];
    __shared__ float ysps[Bq*Cc], ychs[Bq*Cc];
    __shared__ float b1s[32];
    __shared__ float b2s[2];

    int tid = threadIdx.x;
    for (int i = tid; i < 2048; i += 256) {
        int o = i >> 6, c = i & 63;
        w1t[c*32 + o] = sw_w1[i];
    }
    if (tid < 32)  w2p[tid] = pk2(sw_w2[tid], sw_w2[32 + tid]);
    if (tid < 128) { ysps[tid] = g_ysp[tid]; ychs[tid] = g_ych[tid]; }
    if (tid < 32)  b1s[tid] = sw_b1[tid];
    if (tid < 2)   b2s[tid] = sw_b2[tid];
    __syncthreads();

    int p = blockIdx.x * 256 + tid;
    int b = p >> 14, sp = p & 16383;
    const float4* xq  = (const float4*)(g_xt  + (long)p*32);
    const float4* x3q = (const float4*)(g_x3t + (long)p*32);

    float xr[32];
    ull h2[16];
    #pragma unroll
    for (int i = 0; i < 16; i++) h2[i] = pk2(b1s[2*i], b1s[2*i+1]);
    #pragma unroll
    for (int c4 = 0; c4 < 8; c4++) {
        float4 v4 = xq[c4];
        float vs[4] = {v4.x, v4.y, v4.z, v4.w};
        #pragma unroll
        for (int q = 0; q < 4; q++) {
            int c = c4*4 + q;
            xr[c] = vs[q];
            ull v2 = pk2(vs[q], vs[q]);
            const ulonglong2* wp = (const ulonglong2*)(w1t + c*32);
            #pragma unroll
            for (int i = 0; i < 8; i++) {
                ulonglong2 u = wp[i];
                fma2(h2[2*i],   v2, u.x, h2[2*i]);
                fma2(h2[2*i+1], v2, u.y, h2[2*i+1]);
            }
        }
    }
    #pragma unroll
    for (int c4 = 0; c4 < 8; c4++) {
        float4 v4 = x3q[c4];
        float vs[4] = {v4.x, v4.y, v4.z, v4.w};
        #pragma unroll
        for (int q = 0; q < 4; q++) {
            int c = c4*4 + q;
            ull v2 = pk2(vs[q], vs[q]);
            const ulonglong2* wp = (const ulonglong2*)(w1t + (32 + c)*32);
            #pragma unroll
            for (int i = 0; i < 8; i++) {
                ulonglong2 u = wp[i];
                fma2(h2[2*i],   v2, u.x, h2[2*i]);
                fma2(h2[2*i+1], v2, u.y, h2[2*i+1]);
            }
        }
    }
    ull s01 = pk2(b2s[0], b2s[1]);
    #pragma unroll
    for (int i = 0; i < 16; i++) {
        float ha, hb; upk2(ha, hb, h2[i]);
        ha = fmaxf(ha, 0.f); hb = fmaxf(hb, 0.f);
        fma2(s01, pk2(ha, ha), w2p[2*i],   s01);
        fma2(s01, pk2(hb, hb), w2p[2*i+1], s01);
    }
    float s0, s1; upk2(s0, s1, s01);
    s0 = 1.f / (1.f + __expf(-s0));
    s1 = 1.f / (1.f + __expf(-s1));
    const float* yspb = ysps + b*32;
    const float* ychb = ychs + b*32;
    float* op = out + ((long)b << 19) + sp;
    #pragma unroll
    for (int c = 0; c < 32; c++) op[c << 14] = xr[c] + yspb[c]*s0 + ychb[c]*s1;
}

// ---------------- kernel 5: memory attention (per pixel-chunk, per head) ----------------
__global__ __launch_bounds__(256) void k_attn(
    const float* __restrict__ mem, float* __restrict__ out)
{
    __shared__ __align__(16) float ps[MSIZE*HD];  // 16KB
    int tid = threadIdx.x;
    int hd = blockIdx.y;
    const float RSL = 0.35355339059327373f * 1.4426950408889634f;  // rs*log2(e)

    const float* mh = mem + hd*MSIZE*HD;
    for (int i = tid; i < MSIZE*HD; i += 256) {
        int m = i >> 3, d = i & 7;
        ps[((m >> 1)*8 + d)*2 + (m & 1)] = mh[i] * RSL;
    }
    __syncthreads();

    int p = blockIdx.x * 256 + tid;
    int b = p >> 14, sp = p & 16383;
    float* base = out + ((long)b << 19) + ((long)hd*8 << 14) + sp;

    float qv[8];
    #pragma unroll
    for (int d = 0; d < 8; d++) qv[d] = base[d << 14];
    ull q2[8];
    #pragma unroll
    for (int d = 0; d < 8; d++) q2[d] = pk2(qv[d], qv[d]);

    ull r2[8], l2 = 0ULL;
    #pragma unroll
    for (int d = 0; d < 8; d++) r2[d] = 0ULL;

    const ulonglong2* pp = (const ulonglong2*)ps;
    #pragma unroll 8
    for (int j = 0; j < MSIZE/2; j++) {
        ulonglong2 u0 = pp[4*j + 0];
        ulonglong2 u1 = pp[4*j + 1];
        ulonglong2 u2 = pp[4*j + 2];
        ulonglong2 u3 = pp[4*j + 3];
        ull sa, sb;
        mul2(sa, q2[0], u0.x);
        mul2(sb, q2[1], u0.y);
        fma2(sa, q2[2], u1.x, sa);
        fma2(sb, q2[3], u1.y, sb);
        fma2(sa, q2[4], u2.x, sa);
        fma2(sb, q2[5], u2.y, sb);
        fma2(sa, q2[6], u3.x, sa);
        fma2(sb, q2[7], u3.y, sb);
        ull s2; add2(s2, sa, sb);
        float s0, s1; upk2(s0, s1, s2);
        ull e2 = pk2(ex2f(s0), ex2f(s1));
        add2(l2, l2, e2);
        fma2(r2[0], e2, u0.x, r2[0]);
        fma2(r2[1], e2, u0.y, r2[1]);
        fma2(r2[2], e2, u1.x, r2[2]);
        fma2(r2[3], e2, u1.y, r2[3]);
        fma2(r2[4], e2, u2.x, r2[4]);
        fma2(r2[5], e2, u2.y, r2[5]);
        fma2(r2[6], e2, u3.x, r2[6]);
        fma2(r2[7], e2, u3.y, r2[7]);
    }
    float ll, lh; upk2(ll, lh, l2);
    float inv = 1.f / ((ll + lh) * RSL);   // un-scale rec (ps = mem*RSL)
    #pragma unroll
    for (int d = 0; d < 8; d++) {
        float ra, rb; upk2(ra, rb, r2[d]);
        base[d << 14] = qv[d] + (ra + rb) * inv;
    }
}

extern "C" void kernel_launch(void* const* d_in, const int* in_sizes, int n_in,
                              void* d_out, int out_size) {
    const float* x     = (const float*)d_in[0];
    const float* fs_w1 = (const float*)d_in[1];
    const float* fs_w2 = (const float*)d_in[2];
    const float* fc_w1 = (const float*)d_in[3];
    const float* fc_w2 = (const float*)d_in[4];
    const float* sw_w1 = (const float*)d_in[5];
    const float* sw_b1 = (const float*)d_in[6];
    const float* sw_w2 = (const float*)d_in[7];
    const float* sw_b2 = (const float*)d_in[8];
    const float* off_w = (const float*)d_in[9];
    const float* off_b = (const float*)d_in[10];
    const float* dcn_w = (const float*)d_in[11];
    const float* dcn_b = (const float*)d_in[12];
    const float* mem   = (const float*)d_in[13];
    float* out = (float*)d_out;

    k_tr<<<Bq*Hh, 256>>>(x);
    k_avg<<<Bq*Cc, 256>>>(x);
    k_mlp<<<1, 128>>>(fs_w1, fs_w2, fc_w1, fc_w2);
    k_off<<<BHW/256, 256>>>(off_w, off_b);
    k_dcn2<<<BHW/256, 256>>>(dcn_w, dcn_b);
    k_conv<<<BHW/256, 256>>>(sw_w1, sw_b1, sw_w2, sw_b2, out);
    dim3 ag(BHW/256, 4);
    k_attn<<<ag, 256>>>(mem, out);
}

// round 11
// speedup vs baseline: 1.3311x; 1.3311x over previous
#include <cuda_runtime.h>
#include <math.h>

#define Bq 4
#define Cc 32
#define Hh 128
#define Ww 128
#define HW (Hh*Ww)
#define BHW (Bq*HW)
#define MSIZE 512
#define HD 8

typedef unsigned long long ull;

__device__ __forceinline__ ull pk2(float lo, float hi) {
    ull r; asm("mov.b64 %0,{%1,%2};" : "=l"(r) : "f"(lo), "f"(hi)); return r;
}
__device__ __forceinline__ void upk2(float& lo, float& hi, ull v) {
    asm("mov.b64 {%0,%1},%2;" : "=f"(lo), "=f"(hi) : "l"(v));
}
__device__ __forceinline__ void fma2(ull& d, ull a, ull b, ull c) {
    asm("fma.rn.f32x2 %0,%1,%2,%3;" : "=l"(d) : "l"(a), "l"(b), "l"(c));
}
__device__ __forceinline__ void mul2(ull& d, ull a, ull b) {
    asm("mul.rn.f32x2 %0,%1,%2;" : "=l"(d) : "l"(a), "l"(b));
}
__device__ __forceinline__ void add2(ull& d, ull a, ull b) {
    asm("add.rn.f32x2 %0,%1,%2;" : "=l"(d) : "l"(a), "l"(b));
}
__device__ __forceinline__ float ex2f(float x) {
    float r; asm("ex2.approx.f32 %0,%1;" : "=f"(r) : "f"(x)); return r;
}

// scratch (no allocs allowed)
__device__ float g_x3[Bq*Cc*HW];
__device__ float g_om[27*BHW];     // offset-conv output, [j][p]
__device__ float g_yavg[Bq*Cc];
__device__ float g_ysp[Bq*Cc];
__device__ float g_ych[Bq*Cc];

// ---------------- kernel 1: per-(b,c) spatial mean ----------------
__global__ void k_avg(const float* __restrict__ x) {
    int bc = blockIdx.x;
    const float* p = x + bc * HW;
    float s = 0.f;
    for (int i = threadIdx.x; i < HW; i += 256) s += p[i];
    __shared__ float red[256];
    red[threadIdx.x] = s; __syncthreads();
    for (int st = 128; st > 0; st >>= 1) {
        if (threadIdx.x < st) red[threadIdx.x] += red[threadIdx.x + st];
        __syncthreads();
    }
    if (threadIdx.x == 0) g_yavg[bc] = red[0] * (1.0f / (float)HW);
}

// ---------------- kernel 2: tiny squeeze MLPs ----------------
__global__ void k_mlp(const float* __restrict__ fs_w1, const float* __restrict__ fs_w2,
                      const float* __restrict__ fc_w1, const float* __restrict__ fc_w2) {
    __shared__ float ys[Bq*Cc];
    int t = threadIdx.x;           // 128 threads, t = b*32+c
    ys[t] = g_yavg[t];
    __syncthreads();
    int b = t >> 5, c = t & 31;
    const float* yb = ys + b * 32;
    float hs0 = 0.f, hs1 = 0.f;
    #pragma unroll
    for (int j = 0; j < 32; j++) { hs0 += yb[j] * fs_w1[j]; hs1 += yb[j] * fs_w1[32 + j]; }
    hs0 = fmaxf(hs0, 0.f); hs1 = fmaxf(hs1, 0.f);
    float sp = hs0 * fs_w2[c*2 + 0] + hs1 * fs_w2[c*2 + 1];
    g_ysp[t] = 1.f / (1.f + __expf(-sp));
    float ch = 0.f;
    #pragma unroll
    for (int r = 0; r < 4; r++) {
        float a = 0.f;
        #pragma unroll
        for (int j = 0; j < 32; j++) a += yb[j] * fc_w1[r*32 + j];
        ch += fmaxf(a, 0.f) * fc_w2[c*4 + r];
    }
    g_ych[t] = 1.f / (1.f + __expf(-ch));
}

// ---------------- kernel 3a: offset conv (3x3, 32->27) ----------------
// R6 version (best measured): 2 vertically-adjacent pixels per thread,
// NCHW coalesced loads; weight LDS shared by both pixels.
__global__ __launch_bounds__(128) void k_off(
    const float* __restrict__ x,
    const float* __restrict__ off_w, const float* __restrict__ off_b)
{
    __shared__ __align__(16) float wbuf[9*32*28];   // woff[k][c][j28]  32.2KB
    __shared__ float bbuf[28];
    int tid = threadIdx.x;
    // off_w (27,32,9): elem (j,c,k) at j*288+c*9+k -> wbuf[(k*32+c)*28+j]
    for (int i = tid; i < 7776; i += 128) {
        int j = i / 288, r = i - j*288, c = r / 9, k = r - c*9;
        wbuf[(k*32 + c)*28 + j] = off_w[i];
    }
    for (int i = tid; i < 288; i += 128) wbuf[i*28 + 27] = 0.f;
    if (tid < 27) bbuf[tid] = off_b[tid];
    if (tid == 27) bbuf[27] = 0.f;
    __syncthreads();

    int x0i = tid;
    int b  = blockIdx.x >> 6;
    int y0 = (blockIdx.x & 63) * 2;       // rows y0, y0+1
    const float* xb = x + ((long)b << 19);

    ull omA[14], omB[14];
    #pragma unroll
    for (int j = 0; j < 14; j++) { omA[j] = pk2(bbuf[2*j], bbuf[2*j+1]); omB[j] = omA[j]; }

    for (int ky = 0; ky < 3; ky++) {
        int yyA = y0 + ky - 1;
        int yyB = yyA + 1;
        bool okA = (yyA >= 0) & (yyA <= 127);
        bool okB = (yyB >= 0) & (yyB <= 127);
        for (int kx = 0; kx < 3; kx++) {
            int xx = x0i + kx - 1;
            bool okx = (xx >= 0) & (xx <= 127);
            bool vA = okA & okx, vB = okB & okx;
            if (!vA && !vB) continue;
            int kidx = ky*3 + kx;
            const float* xpA = xb + yyA*128 + xx;
            const float* xpB = xpA + 128;
            const float* wb0 = wbuf + kidx*32*28;
            #pragma unroll 4
            for (int c = 0; c < 32; c++) {
                float a = vA ? xpA[c << 14] : 0.f;
                float bb = vB ? xpB[c << 14] : 0.f;
                ull a2 = pk2(a, a), b2 = pk2(bb, bb);
                const ulonglong2* wp = (const ulonglong2*)(wb0 + c*28);
                #pragma unroll
                for (int i = 0; i < 7; i++) {
                    ulonglong2 u = wp[i];
                    fma2(omA[2*i],   a2, u.x, omA[2*i]);
                    fma2(omA[2*i+1], a2, u.y, omA[2*i+1]);
                    fma2(omB[2*i],   b2, u.x, omB[2*i]);
                    fma2(omB[2*i+1], b2, u.y, omB[2*i+1]);
                }
            }
        }
    }
    int pA = (b << 14) + y0*128 + x0i;
    int pB = pA + 128;
    #pragma unroll
    for (int j = 0; j < 14; j++) {
        float a0, a1; upk2(a0, a1, omA[j]);
        float b0, b1; upk2(b0, b1, omB[j]);
        g_om[(2*j)*BHW + pA] = a0;
        g_om[(2*j)*BHW + pB] = b0;
        if (2*j + 1 < 27) {
            g_om[(2*j+1)*BHW + pA] = a1;
            g_om[(2*j+1)*BHW + pB] = b1;
        }
    }
}

// ---------------- kernel 3b: deformable gather + 3x3 conv ----------------
// R4 version (best measured: 74.7us): monolithic 1px/thread, NCHW coalesced
// gathers, smem-transposed weights via LDS.128 + packed fma2.
__global__ __launch_bounds__(256) void k_dcn2(
    const float* __restrict__ x,
    const float* __restrict__ dcn_w, const float* __restrict__ dcn_b)
{
    __shared__ __align__(16) float wbuf[9216];   // wdcn[k][c][o32], 36.9KB
    __shared__ float bbuf[32];
    int tid = threadIdx.x;
    // dcn_w (32,32,9) elem (o,c,k) at o*288+c*9+k -> wbuf[(k*32+c)*32+o]
    for (int i = tid; i < 9216; i += 256) {
        int o = i / 288, r = i - o*288, c = r / 9, k = r - c*9;
        wbuf[(k*32 + c)*32 + o] = dcn_w[i];
    }
    if (tid < 32) bbuf[tid] = dcn_b[tid];
    __syncthreads();

    int p = blockIdx.x * 256 + tid;
    int b = p >> 14;
    int rem = p & 16383;
    int y = rem >> 7, x0i = rem & 127;
    const float* xb = x + ((long)b << 19);

    ull acc2[16];
    #pragma unroll
    for (int i = 0; i < 16; i++) acc2[i] = pk2(bbuf[2*i], bbuf[2*i+1]);

    for (int k = 0; k < 9; k++) {
        float ofy = g_om[(2*k)*BHW + p];
        float ofx = g_om[(2*k+1)*BHW + p];
        float msk = 1.f / (1.f + __expf(-g_om[(18+k)*BHW + p]));
        float py = (float)(y   + k/3 - 1) + ofy;
        float px = (float)(x0i + k%3 - 1) + ofx;
        py = fminf(fmaxf(py, -4.0f), 131.0f);
        px = fminf(fmaxf(px, -4.0f), 131.0f);
        float fy = floorf(py), fx = floorf(px);
        float wy = py - fy, wx = px - fx;
        int iy0 = (int)fy, ix0 = (int)fx, iy1 = iy0 + 1, ix1 = ix0 + 1;
        float vy0 = (iy0 >= 0 && iy0 <= 127) ? 1.f : 0.f;
        float vy1 = (iy1 >= 0 && iy1 <= 127) ? 1.f : 0.f;
        float vx0 = (ix0 >= 0 && ix0 <= 127) ? 1.f : 0.f;
        float vx1 = (ix1 >= 0 && ix1 <= 127) ? 1.f : 0.f;
        float w00 = (1.f - wy) * (1.f - wx) * vy0 * vx0 * msk;
        float w01 = (1.f - wy) * wx         * vy0 * vx1 * msk;
        float w10 = wy         * (1.f - wx) * vy1 * vx0 * msk;
        float w11 = wy         * wx         * vy1 * vx1 * msk;
        int cy0 = min(max(iy0, 0), 127), cy1 = min(max(iy1, 0), 127);
        int cx0 = min(max(ix0, 0), 127), cx1 = min(max(ix1, 0), 127);
        int a00 = cy0*128 + cx0, a01 = cy0*128 + cx1;
        int a10 = cy1*128 + cx0, a11 = cy1*128 + cx1;
        for (int c = 0; c < 32; c++) {
            const float* xp = xb + (c << 14);
            float val = w00 * xp[a00] + w01 * xp[a01] + w10 * xp[a10] + w11 * xp[a11];
            ull v2 = pk2(val, val);
            const ulonglong2* wp = (const ulonglong2*)(wbuf + (k*32 + c)*32);
            #pragma unroll
            for (int i = 0; i < 8; i++) {
                ulonglong2 u = wp[i];
                fma2(acc2[2*i],   v2, u.x, acc2[2*i]);
                fma2(acc2[2*i+1], v2, u.y, acc2[2*i+1]);
            }
        }
    }
    float* x3p = g_x3 + ((long)b << 19) + y*128 + x0i;
    #pragma unroll
    for (int i = 0; i < 16; i++) {
        float a, bfl; upk2(a, bfl, acc2[i]);
        x3p[(2*i) << 14]   = a;
        x3p[(2*i+1) << 14] = bfl;
    }
}

// ---------------- kernel 4: switch-conv + gates -> xo (writes out) ----------------
__global__ __launch_bounds__(256) void k_conv(
    const float* __restrict__ x,
    const float* __restrict__ sw_w1, const float* __restrict__ sw_b1,
    const float* __restrict__ sw_w2, const float* __restrict__ sw_b2,
    float* __restrict__ out)
{
    __shared__ __align__(16) float w1t[64*32];       // transposed: w1t[c][o]
    __shared__ __align__(16) ull   w2p[32];
    __shared__ float ysps[Bq*Cc], ychs[Bq*Cc];
    __shared__ float b1s[32];
    __shared__ float b2s[2];

    int tid = threadIdx.x;
    for (int i = tid; i < 2048; i += 256) {
        int o = i >> 6, c = i & 63;
        w1t[c*32 + o] = sw_w1[i];
    }
    if (tid < 32)  w2p[tid] = pk2(sw_w2[tid], sw_w2[32 + tid]);
    if (tid < 128) { ysps[tid] = g_ysp[tid]; ychs[tid] = g_ych[tid]; }
    if (tid < 32)  b1s[tid] = sw_b1[tid];
    if (tid < 2)   b2s[tid] = sw_b2[tid];
    __syncthreads();

    int p = blockIdx.x * 256 + tid;
    int b = p >> 14, sp = p & 16383;
    const float* xb  = x    + ((long)b << 19) + sp;
    const float* x3b = g_x3 + ((long)b << 19) + sp;

    float xr[32];
    ull h2[16];
    #pragma unroll
    for (int i = 0; i < 16; i++) h2[i] = pk2(b1s[2*i], b1s[2*i+1]);
    #pragma unroll
    for (int c = 0; c < 32; c++) {
        float v = xb[c << 14];
        xr[c] = v;
        ull v2 = pk2(v, v);
        const ulonglong2* wp = (const ulonglong2*)(w1t + c*32);
        #pragma unroll
        for (int i = 0; i < 8; i++) {
            ulonglong2 u = wp[i];
            fma2(h2[2*i],   v2, u.x, h2[2*i]);
            fma2(h2[2*i+1], v2, u.y, h2[2*i+1]);
        }
    }
    #pragma unroll
    for (int c = 0; c < 32; c++) {
        float v = x3b[c << 14];
        ull v2 = pk2(v, v);
        const ulonglong2* wp = (const ulonglong2*)(w1t + (32 + c)*32);
        #pragma unroll
        for (int i = 0; i < 8; i++) {
            ulonglong2 u = wp[i];
            fma2(h2[2*i],   v2, u.x, h2[2*i]);
            fma2(h2[2*i+1], v2, u.y, h2[2*i+1]);
        }
    }
    ull s01 = pk2(b2s[0], b2s[1]);
    #pragma unroll
    for (int i = 0; i < 16; i++) {
        float ha, hb; upk2(ha, hb, h2[i]);
        ha = fmaxf(ha, 0.f); hb = fmaxf(hb, 0.f);
        fma2(s01, pk2(ha, ha), w2p[2*i],   s01);
        fma2(s01, pk2(hb, hb), w2p[2*i+1], s01);
    }
    float s0, s1; upk2(s0, s1, s01);
    s0 = 1.f / (1.f + __expf(-s0));
    s1 = 1.f / (1.f + __expf(-s1));
    const float* yspb = ysps + b*32;
    const float* ychb = ychs + b*32;
    float* op = out + ((long)b << 19) + sp;
    #pragma unroll
    for (int c = 0; c < 32; c++) op[c << 14] = xr[c] + yspb[c]*s0 + ychb[c]*s1;
}

// ---------------- kernel 5: memory attention (per pixel-chunk, per head) ----------------
__global__ __launch_bounds__(256) void k_attn(
    const float* __restrict__ mem, float* __restrict__ out)
{
    __shared__ __align__(16) float ps[MSIZE*HD];  // 16KB
    int tid = threadIdx.x;
    int hd = blockIdx.y;
    const float RSL = 0.35355339059327373f * 1.4426950408889634f;  // rs*log2(e)

    const float* mh = mem + hd*MSIZE*HD;
    for (int i = tid; i < MSIZE*HD; i += 256) {
        int m = i >> 3, d = i & 7;
        ps[((m >> 1)*8 + d)*2 + (m & 1)] = mh[i] * RSL;
    }
    __syncthreads();

    int p = blockIdx.x * 256 + tid;
    int b = p >> 14, sp = p & 16383;
    float* base = out + ((long)b << 19) + ((long)hd*8 << 14) + sp;

    float qv[8];
    #pragma unroll
    for (int d = 0; d < 8; d++) qv[d] = base[d << 14];
    ull q2[8];
    #pragma unroll
    for (int d = 0; d < 8; d++) q2[d] = pk2(qv[d], qv[d]);

    ull r2[8], l2 = 0ULL;
    #pragma unroll
    for (int d = 0; d < 8; d++) r2[d] = 0ULL;

    const ulonglong2* pp = (const ulonglong2*)ps;
    #pragma unroll 8
    for (int j = 0; j < MSIZE/2; j++) {
        ulonglong2 u0 = pp[4*j + 0];
        ulonglong2 u1 = pp[4*j + 1];
        ulonglong2 u2 = pp[4*j + 2];
        ulonglong2 u3 = pp[4*j + 3];
        ull sa, sb;
        mul2(sa, q2[0], u0.x);
        mul2(sb, q2[1], u0.y);
        fma2(sa, q2[2], u1.x, sa);
        fma2(sb, q2[3], u1.y, sb);
        fma2(sa, q2[4], u2.x, sa);
        fma2(sb, q2[5], u2.y, sb);
        fma2(sa, q2[6], u3.x, sa);
        fma2(sb, q2[7], u3.y, sb);
        ull s2; add2(s2, sa, sb);
        float s0, s1; upk2(s0, s1, s2);
        ull e2 = pk2(ex2f(s0), ex2f(s1));
        add2(l2, l2, e2);
        fma2(r2[0], e2, u0.x, r2[0]);
        fma2(r2[1], e2, u0.y, r2[1]);
        fma2(r2[2], e2, u1.x, r2[2]);
        fma2(r2[3], e2, u1.y, r2[3]);
        fma2(r2[4], e2, u2.x, r2[4]);
        fma2(r2[5], e2, u2.y, r2[5]);
        fma2(r2[6], e2, u3.x, r2[6]);
        fma2(r2[7], e2, u3.y, r2[7]);
    }
    float ll, lh; upk2(ll, lh, l2);
    float inv = 1.f / ((ll + lh) * RSL);   // un-scale rec (ps = mem*RSL)
    #pragma unroll
    for (int d = 0; d < 8; d++) {
        float ra, rb; upk2(ra, rb, r2[d]);
        base[d << 14] = qv[d] + (ra + rb) * inv;
    }
}

extern "C" void kernel_launch(void* const* d_in, const int* in_sizes, int n_in,
                              void* d_out, int out_size) {
    const float* x     = (const float*)d_in[0];
    const float* fs_w1 = (const float*)d_in[1];
    const float* fs_w2 = (const float*)d_in[2];
    const float* fc_w1 = (const float*)d_in[3];
    const float* fc_w2 = (const float*)d_in[4];
    const float* sw_w1 = (const float*)d_in[5];
    const float* sw_b1 = (const float*)d_in[6];
    const float* sw_w2 = (const float*)d_in[7];
    const float* sw_b2 = (const float*)d_in[8];
    const float* off_w = (const float*)d_in[9];
    const float* off_b = (const float*)d_in[10];
    const float* dcn_w = (const float*)d_in[11];
    const float* dcn_b = (const float*)d_in[12];
    const float* mem   = (const float*)d_in[13];
    float* out = (float*)d_out;

    k_avg<<<Bq*Cc, 256>>>(x);
    k_mlp<<<1, 128>>>(fs_w1, fs_w2, fc_w1, fc_w2);
    k_off<<<256, 128>>>(x, off_w, off_b);
    k_dcn2<<<BHW/256, 256>>>(x, dcn_w, dcn_b);
    k_conv<<<BHW/256, 256>>>(x, sw_w1, sw_b1, sw_w2, sw_b2, out);
    dim3 ag(BHW/256, 4);
    k_attn<<<ag, 256>>>(mem, out);
}

// round 12
// speedup vs baseline: 1.7924x; 1.3465x over previous
#include <cuda_runtime.h>
#include <math.h>
#include <stdint.h>

#define Bq 4
#define Cc 32
#define Hh 128
#define Ww 128
#define HW (Hh*Ww)
#define BHW (Bq*HW)
#define MSIZE 512
#define HD 8

typedef unsigned long long ull;

__device__ __forceinline__ ull pk2(float lo, float hi) {
    ull r; asm("mov.b64 %0,{%1,%2};" : "=l"(r) : "f"(lo), "f"(hi)); return r;
}
__device__ __forceinline__ void upk2(float& lo, float& hi, ull v) {
    asm("mov.b64 {%0,%1},%2;" : "=f"(lo), "=f"(hi) : "l"(v));
}
__device__ __forceinline__ void fma2(ull& d, ull a, ull b, ull c) {
    asm("fma.rn.f32x2 %0,%1,%2,%3;" : "=l"(d) : "l"(a), "l"(b), "l"(c));
}
__device__ __forceinline__ float ex2f(float x) {
    float r; asm("ex2.approx.f32 %0,%1;" : "=f"(r) : "f"(x)); return r;
}
__device__ __forceinline__ uint32_t tf32c(float f) {
    uint32_t r; asm("cvt.rna.tf32.f32 %0,%1;" : "=r"(r) : "f"(f)); return r;
}
#define MMA168(d0,d1,d2,d3,a0,a1,a2,a3,b0,b1) \
  asm("mma.sync.aligned.m16n8k8.row.col.f32.tf32.tf32.f32 " \
      "{%0,%1,%2,%3}, {%4,%5,%6,%7}, {%8,%9}, {%0,%1,%2,%3};" \
      : "+f"(d0),"+f"(d1),"+f"(d2),"+f"(d3) \
      : "r"(a0),"r"(a1),"r"(a2),"r"(a3),"r"(b0),"r"(b1))

// scratch (no allocs allowed)
__device__ float g_x3[Bq*Cc*HW];
__device__ float g_om[27*BHW];     // offset-conv output, [j][p]
__device__ float g_yavg[Bq*Cc];
__device__ float g_ysp[Bq*Cc];
__device__ float g_ych[Bq*Cc];

// ---------------- kernel 1: per-(b,c) spatial mean ----------------
__global__ void k_avg(const float* __restrict__ x) {
    int bc = blockIdx.x;
    const float* p = x + bc * HW;
    float s = 0.f;
    for (int i = threadIdx.x; i < HW; i += 256) s += p[i];
    __shared__ float red[256];
    red[threadIdx.x] = s; __syncthreads();
    for (int st = 128; st > 0; st >>= 1) {
        if (threadIdx.x < st) red[threadIdx.x] += red[threadIdx.x + st];
        __syncthreads();
    }
    if (threadIdx.x == 0) g_yavg[bc] = red[0] * (1.0f / (float)HW);
}

// ---------------- kernel 2: tiny squeeze MLPs ----------------
__global__ void k_mlp(const float* __restrict__ fs_w1, const float* __restrict__ fs_w2,
                      const float* __restrict__ fc_w1, const float* __restrict__ fc_w2) {
    __shared__ float ys[Bq*Cc];
    int t = threadIdx.x;           // 128 threads, t = b*32+c
    ys[t] = g_yavg[t];
    __syncthreads();
    int b = t >> 5, c = t & 31;
    const float* yb = ys + b * 32;
    float hs0 = 0.f, hs1 = 0.f;
    #pragma unroll
    for (int j = 0; j < 32; j++) { hs0 += yb[j] * fs_w1[j]; hs1 += yb[j] * fs_w1[32 + j]; }
    hs0 = fmaxf(hs0, 0.f); hs1 = fmaxf(hs1, 0.f);
    float sp = hs0 * fs_w2[c*2 + 0] + hs1 * fs_w2[c*2 + 1];
    g_ysp[t] = 1.f / (1.f + __expf(-sp));
    float ch = 0.f;
    #pragma unroll
    for (int r = 0; r < 4; r++) {
        float a = 0.f;
        #pragma unroll
        for (int j = 0; j < 32; j++) a += yb[j] * fc_w1[r*32 + j];
        ch += fmaxf(a, 0.f) * fc_w2[c*4 + r];
    }
    g_ych[t] = 1.f / (1.f + __expf(-ch));
}

// ---------------- kernel 3a: offset conv (3x3, 32->27) ----------------
__global__ __launch_bounds__(128) void k_off(
    const float* __restrict__ x,
    const float* __restrict__ off_w, const float* __restrict__ off_b)
{
    __shared__ __align__(16) float wbuf[9*32*28];
    __shared__ float bbuf[28];
    int tid = threadIdx.x;
    for (int i = tid; i < 7776; i += 128) {
        int j = i / 288, r = i - j*288, c = r / 9, k = r - c*9;
        wbuf[(k*32 + c)*28 + j] = off_w[i];
    }
    for (int i = tid; i < 288; i += 128) wbuf[i*28 + 27] = 0.f;
    if (tid < 27) bbuf[tid] = off_b[tid];
    if (tid == 27) bbuf[27] = 0.f;
    __syncthreads();

    int x0i = tid;
    int b  = blockIdx.x >> 6;
    int y0 = (blockIdx.x & 63) * 2;
    const float* xb = x + ((long)b << 19);

    ull omA[14], omB[14];
    #pragma unroll
    for (int j = 0; j < 14; j++) { omA[j] = pk2(bbuf[2*j], bbuf[2*j+1]); omB[j] = omA[j]; }

    for (int ky = 0; ky < 3; ky++) {
        int yyA = y0 + ky - 1;
        int yyB = yyA + 1;
        bool okA = (yyA >= 0) & (yyA <= 127);
        bool okB = (yyB >= 0) & (yyB <= 127);
        for (int kx = 0; kx < 3; kx++) {
            int xx = x0i + kx - 1;
            bool okx = (xx >= 0) & (xx <= 127);
            bool vA = okA & okx, vB = okB & okx;
            if (!vA && !vB) continue;
            int kidx = ky*3 + kx;
            const float* xpA = xb + yyA*128 + xx;
            const float* xpB = xpA + 128;
            const float* wb0 = wbuf + kidx*32*28;
            #pragma unroll 4
            for (int c = 0; c < 32; c++) {
                float a = vA ? xpA[c << 14] : 0.f;
                float bb = vB ? xpB[c << 14] : 0.f;
                ull a2 = pk2(a, a), b2 = pk2(bb, bb);
                const ulonglong2* wp = (const ulonglong2*)(wb0 + c*28);
                #pragma unroll
                for (int i = 0; i < 7; i++) {
                    ulonglong2 u = wp[i];
                    fma2(omA[2*i],   a2, u.x, omA[2*i]);
                    fma2(omA[2*i+1], a2, u.y, omA[2*i+1]);
                    fma2(omB[2*i],   b2, u.x, omB[2*i]);
                    fma2(omB[2*i+1], b2, u.y, omB[2*i+1]);
                }
            }
        }
    }
    int pA = (b << 14) + y0*128 + x0i;
    int pB = pA + 128;
    #pragma unroll
    for (int j = 0; j < 14; j++) {
        float a0, a1; upk2(a0, a1, omA[j]);
        float b0, b1; upk2(b0, b1, omB[j]);
        g_om[(2*j)*BHW + pA] = a0;
        g_om[(2*j)*BHW + pB] = b0;
        if (2*j + 1 < 27) {
            g_om[(2*j+1)*BHW + pA] = a1;
            g_om[(2*j+1)*BHW + pB] = b1;
        }
    }
}

// ---------------- kernel 3b: deformable gather + 3x3 conv (R4 best) ----------------
__global__ __launch_bounds__(256) void k_dcn2(
    const float* __restrict__ x,
    const float* __restrict__ dcn_w, const float* __restrict__ dcn_b)
{
    __shared__ __align__(16) float wbuf[9216];
    __shared__ float bbuf[32];
    int tid = threadIdx.x;
    for (int i = tid; i < 9216; i += 256) {
        int o = i / 288, r = i - o*288, c = r / 9, k = r - c*9;
        wbuf[(k*32 + c)*32 + o] = dcn_w[i];
    }
    if (tid < 32) bbuf[tid] = dcn_b[tid];
    __syncthreads();

    int p = blockIdx.x * 256 + tid;
    int b = p >> 14;
    int rem = p & 16383;
    int y = rem >> 7, x0i = rem & 127;
    const float* xb = x + ((long)b << 19);

    ull acc2[16];
    #pragma unroll
    for (int i = 0; i < 16; i++) acc2[i] = pk2(bbuf[2*i], bbuf[2*i+1]);

    for (int k = 0; k < 9; k++) {
        float ofy = g_om[(2*k)*BHW + p];
        float ofx = g_om[(2*k+1)*BHW + p];
        float msk = 1.f / (1.f + __expf(-g_om[(18+k)*BHW + p]));
        float py = (float)(y   + k/3 - 1) + ofy;
        float px = (float)(x0i + k%3 - 1) + ofx;
        py = fminf(fmaxf(py, -4.0f), 131.0f);
        px = fminf(fmaxf(px, -4.0f), 131.0f);
        float fy = floorf(py), fx = floorf(px);
        float wy = py - fy, wx = px - fx;
        int iy0 = (int)fy, ix0 = (int)fx, iy1 = iy0 + 1, ix1 = ix0 + 1;
        float vy0 = (iy0 >= 0 && iy0 <= 127) ? 1.f : 0.f;
        float vy1 = (iy1 >= 0 && iy1 <= 127) ? 1.f : 0.f;
        float vx0 = (ix0 >= 0 && ix0 <= 127) ? 1.f : 0.f;
        float vx1 = (ix1 >= 0 && ix1 <= 127) ? 1.f : 0.f;
        float w00 = (1.f - wy) * (1.f - wx) * vy0 * vx0 * msk;
        float w01 = (1.f - wy) * wx         * vy0 * vx1 * msk;
        float w10 = wy         * (1.f - wx) * vy1 * vx0 * msk;
        float w11 = wy         * wx         * vy1 * vx1 * msk;
        int cy0 = min(max(iy0, 0), 127), cy1 = min(max(iy1, 0), 127);
        int cx0 = min(max(ix0, 0), 127), cx1 = min(max(ix1, 0), 127);
        int a00 = cy0*128 + cx0, a01 = cy0*128 + cx1;
        int a10 = cy1*128 + cx0, a11 = cy1*128 + cx1;
        for (int c = 0; c < 32; c++) {
            const float* xp = xb + (c << 14);
            float val = w00 * xp[a00] + w01 * xp[a01] + w10 * xp[a10] + w11 * xp[a11];
            ull v2 = pk2(val, val);
            const ulonglong2* wp = (const ulonglong2*)(wbuf + (k*32 + c)*32);
            #pragma unroll
            for (int i = 0; i < 8; i++) {
                ulonglong2 u = wp[i];
                fma2(acc2[2*i],   v2, u.x, acc2[2*i]);
                fma2(acc2[2*i+1], v2, u.y, acc2[2*i+1]);
            }
        }
    }
    float* x3p = g_x3 + ((long)b << 19) + y*128 + x0i;
    #pragma unroll
    for (int i = 0; i < 16; i++) {
        float a, bfl; upk2(a, bfl, acc2[i]);
        x3p[(2*i) << 14]   = a;
        x3p[(2*i+1) << 14] = bfl;
    }
}

// ---------------- kernel 4: switch-conv + gates -> xo (writes out) ----------------
__global__ __launch_bounds__(256) void k_conv(
    const float* __restrict__ x,
    const float* __restrict__ sw_w1, const float* __restrict__ sw_b1,
    const float* __restrict__ sw_w2, const float* __restrict__ sw_b2,
    float* __restrict__ out)
{
    __shared__ __align__(16) float w1t[64*32];
    __shared__ __align__(16) ull   w2p[32];
    __shared__ float ysps[Bq*Cc], ychs[Bq*Cc];
    __shared__ float b1s[32];
    __shared__ float b2s[2];

    int tid = threadIdx.x;
    for (int i = tid; i < 2048; i += 256) {
        int o = i >> 6, c = i & 63;
        w1t[c*32 + o] = sw_w1[i];
    }
    if (tid < 32)  w2p[tid] = pk2(sw_w2[tid], sw_w2[32 + tid]);
    if (tid < 128) { ysps[tid] = g_ysp[tid]; ychs[tid] = g_ych[tid]; }
    if (tid < 32)  b1s[tid] = sw_b1[tid];
    if (tid < 2)   b2s[tid] = sw_b2[tid];
    __syncthreads();

    int p = blockIdx.x * 256 + tid;
    int b = p >> 14, sp = p & 16383;
    const float* xb  = x    + ((long)b << 19) + sp;
    const float* x3b = g_x3 + ((long)b << 19) + sp;

    float xr[32];
    ull h2[16];
    #pragma unroll
    for (int i = 0; i < 16; i++) h2[i] = pk2(b1s[2*i], b1s[2*i+1]);
    #pragma unroll
    for (int c = 0; c < 32; c++) {
        float v = xb[c << 14];
        xr[c] = v;
        ull v2 = pk2(v, v);
        const ulonglong2* wp = (const ulonglong2*)(w1t + c*32);
        #pragma unroll
        for (int i = 0; i < 8; i++) {
            ulonglong2 u = wp[i];
            fma2(h2[2*i],   v2, u.x, h2[2*i]);
            fma2(h2[2*i+1], v2, u.y, h2[2*i+1]);
        }
    }
    #pragma unroll
    for (int c = 0; c < 32; c++) {
        float v = x3b[c << 14];
        ull v2 = pk2(v, v);
        const ulonglong2* wp = (const ulonglong2*)(w1t + (32 + c)*32);
        #pragma unroll
        for (int i = 0; i < 8; i++) {
            ulonglong2 u = wp[i];
            fma2(h2[2*i],   v2, u.x, h2[2*i]);
            fma2(h2[2*i+1], v2, u.y, h2[2*i+1]);
        }
    }
    ull s01 = pk2(b2s[0], b2s[1]);
    #pragma unroll
    for (int i = 0; i < 16; i++) {
        float ha, hb; upk2(ha, hb, h2[i]);
        ha = fmaxf(ha, 0.f); hb = fmaxf(hb, 0.f);
        fma2(s01, pk2(ha, ha), w2p[2*i],   s01);
        fma2(s01, pk2(hb, hb), w2p[2*i+1], s01);
    }
    float s0, s1; upk2(s0, s1, s01);
    s0 = 1.f / (1.f + __expf(-s0));
    s1 = 1.f / (1.f + __expf(-s1));
    const float* yspb = ysps + b*32;
    const float* ychb = ychs + b*32;
    float* op = out + ((long)b << 19) + sp;
    #pragma unroll
    for (int c = 0; c < 32; c++) op[c << 14] = xr[c] + yspb[c]*s0 + ychb[c]*s1;
}

// ---------------- kernel 5: memory attention via tf32 tensor cores ----------------
// Block = 128 pixels x 1 head; 8 warps, each warp owns 16 pixels (m16).
// Loop over 64 slot-tiles (n=8): mma1 S=Q@M1, ex2 in-register, mma2 rec+=P@M2.
// mma1 B columns permuted by SIG so its D fragment IS mma2's A fragment.
__global__ __launch_bounds__(256) void k_attn(
    const float* __restrict__ mem, float* __restrict__ out)
{
    __shared__ __align__(16) uint2 b1buf[64*32];  // 16KB, per-lane frag of M*RSL (permuted cols)
    __shared__ __align__(16) uint2 b2buf[64*32];  // 16KB, per-lane frag of M (natural rows)
    int tid = threadIdx.x;
    int hd = blockIdx.y;
    const float RSL = 0.35355339059327373f * 1.4426950408889634f;  // rs*log2(e)
    const int SIG[8] = {0,4,1,5,2,6,3,7};

    const float* mh = mem + hd*MSIZE*HD;
    for (int j = tid; j < 2048; j += 256) {
        int t = j >> 5, i = j & 31;
        int c = i >> 2, r = i & 3;        // frag col = lane/4, frag row = lane%4
        int s1 = 8*t + SIG[c];
        b1buf[j] = make_uint2(tf32c(mh[s1*8 + r] * RSL), tf32c(mh[s1*8 + r + 4] * RSL));
        b2buf[j] = make_uint2(tf32c(mh[(8*t + r)*8 + c]), tf32c(mh[(8*t + r + 4)*8 + c]));
    }
    __syncthreads();

    int w = tid >> 5, lane = tid & 31;
    int p0 = blockIdx.x * 128 + w * 16;   // warp's first pixel
    int b = p0 >> 14, sp0 = p0 & 16383;
    int r = lane >> 2, q = lane & 3;
    long base = ((long)b << 19) + ((long)(hd*8) << 14);
    int spA = sp0 + r, spB = sp0 + r + 8;

    // Q fragment: rows (r, r+8), cols (q, q+4)
    uint32_t a0 = tf32c(out[base + ((long)q << 14) + spA]);
    uint32_t a1 = tf32c(out[base + ((long)q << 14) + spB]);
    uint32_t a2 = tf32c(out[base + ((long)(q+4) << 14) + spA]);
    uint32_t a3 = tf32c(out[base + ((long)(q+4) << 14) + spB]);

    float cE0=0.f,cE1=0.f,cE2=0.f,cE3=0.f;
    float cO0=0.f,cO1=0.f,cO2=0.f,cO3=0.f;
    float ls0 = 0.f, ls1 = 0.f;

    #pragma unroll 4
    for (int t = 0; t < 64; t += 2) {
        {
            uint2 b1 = b1buf[t*32 + lane];
            float s0=0.f,s1v=0.f,s2=0.f,s3=0.f;
            MMA168(s0,s1v,s2,s3, a0,a1,a2,a3, b1.x,b1.y);
            float e0 = ex2f(s0), e1 = ex2f(s1v), e2 = ex2f(s2), e3 = ex2f(s3);
            ls0 += e0 + e1; ls1 += e2 + e3;
            uint32_t pa0 = tf32c(e0), pa1 = tf32c(e2), pa2 = tf32c(e1), pa3 = tf32c(e3);
            uint2 b2 = b2buf[t*32 + lane];
            MMA168(cE0,cE1,cE2,cE3, pa0,pa1,pa2,pa3, b2.x,b2.y);
        }
        {
            uint2 b1 = b1buf[(t+1)*32 + lane];
            float s0=0.f,s1v=0.f,s2=0.f,s3=0.f;
            MMA168(s0,s1v,s2,s3, a0,a1,a2,a3, b1.x,b1.y);
            float e0 = ex2f(s0), e1 = ex2f(s1v), e2 = ex2f(s2), e3 = ex2f(s3);
            ls0 += e0 + e1; ls1 += e2 + e3;
            uint32_t pa0 = tf32c(e0), pa1 = tf32c(e2), pa2 = tf32c(e1), pa3 = tf32c(e3);
            uint2 b2 = b2buf[(t+1)*32 + lane];
            MMA168(cO0,cO1,cO2,cO3, pa0,pa1,pa2,pa3, b2.x,b2.y);
        }
    }
    float c0 = cE0 + cO0, c1 = cE1 + cO1, c2 = cE2 + cO2, c3 = cE3 + cO3;

    // row sums: reduce over the 4 lanes of the quad (lanes differ in bits 0,1)
    ls0 += __shfl_xor_sync(0xffffffffu, ls0, 1);
    ls0 += __shfl_xor_sync(0xffffffffu, ls0, 2);
    ls1 += __shfl_xor_sync(0xffffffffu, ls1, 1);
    ls1 += __shfl_xor_sync(0xffffffffu, ls1, 2);
    float inv0 = 1.f / ls0, inv1 = 1.f / ls1;

    // write back: cols (2q, 2q+1), rows (spA, spB); RMW (out holds xo)
    long oA0 = base + ((long)(2*q)   << 14) + spA;
    long oA1 = base + ((long)(2*q+1) << 14) + spA;
    long oB0 = base + ((long)(2*q)   << 14) + spB;
    long oB1 = base + ((long)(2*q+1) << 14) + spB;
    out[oA0] += c0 * inv0;
    out[oA1] += c1 * inv0;
    out[oB0] += c2 * inv1;
    out[oB1] += c3 * inv1;
}

extern "C" void kernel_launch(void* const* d_in, const int* in_sizes, int n_in,
                              void* d_out, int out_size) {
    const float* x     = (const float*)d_in[0];
    const float* fs_w1 = (const float*)d_in[1];
    const float* fs_w2 = (const float*)d_in[2];
    const float* fc_w1 = (const float*)d_in[3];
    const float* fc_w2 = (const float*)d_in[4];
    const float* sw_w1 = (const float*)d_in[5];
    const float* sw_b1 = (const float*)d_in[6];
    const float* sw_w2 = (const float*)d_in[7];
    const float* sw_b2 = (const float*)d_in[8];
    const float* off_w = (const float*)d_in[9];
    const float* off_b = (const float*)d_in[10];
    const float* dcn_w = (const float*)d_in[11];
    const float* dcn_b = (const float*)d_in[12];
    const float* mem   = (const float*)d_in[13];
    float* out = (float*)d_out;

    k_avg<<<Bq*Cc, 256>>>(x);
    k_mlp<<<1, 128>>>(fs_w1, fs_w2, fc_w1, fc_w2);
    k_off<<<256, 128>>>(x, off_w, off_b);
    k_dcn2<<<BHW/256, 256>>>(x, dcn_w, dcn_b);
    k_conv<<<BHW/256, 256>>>(x, sw_w1, sw_b1, sw_w2, sw_b2, out);
    dim3 ag(BHW/128, 4);
    k_attn<<<ag, 256>>>(mem, out);
}